// round 6
// baseline (speedup 1.0000x reference)
#include <cuda_runtime.h>
#include <cuda_bf16.h>
#include <cstdint>

// B=8, N=4096, C=1024, H=16, d=64, Hf=2048; M = B*N = 32768 rows.
#define M_ROWS 32768
#define C_DIM  1024
#define HF_DIM 2048
#define N_SEQ  4096
#define QKV_STRIDE 3072

// tcgen05 is arch-specific ("a"-target) only; hide from plain compute_103 pass.
#if defined(__CUDA_ARCH_FEAT_SM103_ALL) || defined(__CUDA_ARCH_FEAT_SM100_ALL) || defined(__CUDA_ARCH_SPECIFIC__)
#define TCOK 1
#else
#define TCOK 0
#endif

// ================= PTX helpers =================
__device__ __forceinline__ uint32_t smem_to_u32(const void* p) {
    uint32_t a;
    asm("{ .reg .u64 t; cvta.to.shared.u64 t, %1; cvt.u32.u64 %0, t; }" : "=r"(a) : "l"(p));
    return a;
}
__device__ __forceinline__ uint32_t elect_one_pred() {
    uint32_t p;
    asm volatile("{\n\t.reg .pred p;\n\telect.sync _|p, 0xFFFFFFFF;\n\tselp.b32 %0, 1, 0, p;\n\t}" : "=r"(p));
    return p;
}
__device__ __forceinline__ uint32_t cluster_rank() {
    uint32_t r;
    asm("mov.u32 %0, %%cluster_ctarank;" : "=r"(r));
    return r;
}
#define MBARRIER_INIT(addr, cnt) \
    asm volatile("mbarrier.init.shared.b64 [%0], %1;" :: "r"((uint32_t)(addr)), "r"((uint32_t)(cnt)) : "memory")
#define MBARRIER_WAIT_PARITY(mbar_smem_addr, phase_parity) do { \
    uint32_t _mbar = (uint32_t)(mbar_smem_addr); \
    uint32_t _parity = (uint32_t)(phase_parity); \
    uint32_t _done; \
    asm volatile("{\n\t.reg .pred p;\n\tmbarrier.try_wait.parity.acquire.cta.shared::cta.b64 p, [%1], %2;\n\tselp.b32 %0, 1, 0, p;\n\t}" \
        : "=r"(_done) : "r"(_mbar), "r"(_parity) : "memory"); \
    if (!_done) { \
        asm volatile("{\n\t.reg .pred P1;\n\tWAIT_LOOP_%=:\n\tmbarrier.try_wait.parity.acquire.cta.shared::cta.b64 P1, [%0], %1, 0x989680;\n\t@P1 bra.uni WAIT_DONE_%=;\n\tbra.uni WAIT_LOOP_%=;\n\tWAIT_DONE_%=:\n\t}" \
            :: "r"(_mbar), "r"(_parity) : "memory"); \
    } \
} while(0)
#define FENCE_PROXY() asm volatile("fence.proxy.async.shared::cta;" ::: "memory")
#define CP_ASYNC16(saddr, gptr) \
    asm volatile("cp.async.cg.shared.global [%0], [%1], 16;" :: "r"((uint32_t)(saddr)), "l"(gptr) : "memory")
#define CP_COMMIT() asm volatile("cp.async.commit_group;" ::: "memory")
#define CP_WAIT0()  asm volatile("cp.async.wait_group 0;" ::: "memory")
#define CLUSTER_SYNC() do { \
    asm volatile("barrier.cluster.arrive.aligned;" ::: "memory"); \
    asm volatile("barrier.cluster.wait.aligned;" ::: "memory"); \
} while(0)

#if TCOK
#define TCGEN05_ALLOC_CG2(smem_addr, nCols) \
    asm volatile("tcgen05.alloc.cta_group::2.sync.aligned.shared::cta.b32 [%0], %1;" \
        :: "r"((uint32_t)(smem_addr)), "r"((uint32_t)(nCols)) : "memory")
#define TCGEN05_DEALLOC_CG2(tmem_addr, nCols) \
    asm volatile("tcgen05.dealloc.cta_group::2.sync.aligned.b32 %0, %1;" :: "r"(tmem_addr), "r"((uint32_t)(nCols)))
#define TCGEN05_RELINQUISH_CG2() \
    asm volatile("tcgen05.relinquish_alloc_permit.cta_group::2.sync.aligned;")
#define TCGEN05_COMMIT_MC2(mbar) \
    asm volatile("tcgen05.commit.cta_group::2.mbarrier::arrive::one.shared::cluster.multicast::cluster.b64 [%0], %1;" \
        :: "r"((uint32_t)(mbar)), "h"((uint16_t)3) : "memory")
#define TCGEN05_WAIT_LD()  asm volatile("tcgen05.wait::ld.sync.aligned;" ::: "memory")
#define TCGEN05_FENCE_AFTER()  asm volatile("tcgen05.fence::after_thread_sync;" ::: "memory")
#define TCGEN05_LD_32X32B_X32(r, tmem_addr) \
    asm volatile("tcgen05.ld.sync.aligned.32x32b.x32.b32 " \
        "{%0, %1, %2, %3, %4, %5, %6, %7, %8, %9, %10, %11, %12, %13, %14, %15, " \
        " %16, %17, %18, %19, %20, %21, %22, %23, %24, %25, %26, %27, %28, %29, %30, %31}, [%32];" \
        : "=r"((r)[0]),  "=r"((r)[1]),  "=r"((r)[2]),  "=r"((r)[3]), \
          "=r"((r)[4]),  "=r"((r)[5]),  "=r"((r)[6]),  "=r"((r)[7]), \
          "=r"((r)[8]),  "=r"((r)[9]),  "=r"((r)[10]), "=r"((r)[11]), \
          "=r"((r)[12]), "=r"((r)[13]), "=r"((r)[14]), "=r"((r)[15]), \
          "=r"((r)[16]), "=r"((r)[17]), "=r"((r)[18]), "=r"((r)[19]), \
          "=r"((r)[20]), "=r"((r)[21]), "=r"((r)[22]), "=r"((r)[23]), \
          "=r"((r)[24]), "=r"((r)[25]), "=r"((r)[26]), "=r"((r)[27]), \
          "=r"((r)[28]), "=r"((r)[29]), "=r"((r)[30]), "=r"((r)[31]) \
        : "r"(tmem_addr))

// cg2 SS-mode f16-kind MMA (bf16 inputs, f32 accum), M spans both CTAs
__device__ __forceinline__ void mma_f16_ss_cg2(uint32_t d_tmem, uint64_t a_desc, uint64_t b_desc,
                                               uint32_t idesc, bool accum) {
    uint32_t en = accum ? 1u : 0u;
    asm volatile(
        "{\n\t.reg .pred p;\n\tsetp.ne.u32 p, %5, 0;\n\t"
        "tcgen05.mma.cta_group::2.kind::f16 [%0], %1, %2, %3, {%4, %4, %4, %4, %4, %4, %4, %4}, p;\n\t}"
        :: "r"(d_tmem), "l"(a_desc), "l"(b_desc), "r"(idesc), "r"(0u), "r"(en)
        : "memory");
}
#endif  // TCOK

#define SMEM_SWIZZLE_128B(b) ((b) ^ (((b) >> 3) & 0x70))
static constexpr uint64_t SMEM_DESC_BASE_SW128 =
    (uint64_t(2) << 61) | (uint64_t(1) << 46) | (uint64_t(64) << 32) | (uint64_t(1) << 16);
#define MAKE_SMEM_DESC(base_addr) (SMEM_DESC_BASE_SW128 | ((uint64_t)((base_addr) >> 4) & 0x3FFF))

__device__ __forceinline__ void split_bf16(float v, __nv_bfloat16& hi, __nv_bfloat16& lo) {
    hi = __float2bfloat16(v);
    lo = __float2bfloat16(v - __bfloat162float(hi));
}
__device__ __forceinline__ float gelu_exact(float x) {
    return 0.5f * x * (1.0f + erff(x * 0.70710678118654752440f));
}

// ================= scratch =================
__device__ __nv_bfloat16 g_h_hi[33554432],  g_h_lo[33554432];     // LN1 out
__device__ float         g_qkv[100663296];                        // Q|K|V  (M, 3072)
__device__ __nv_bfloat16 g_o_hi[33554432],  g_o_lo[33554432];     // attn out (permuted)
__device__ float         g_x1[33554432];
__device__ __nv_bfloat16 g_h2_hi[33554432], g_h2_lo[33554432];    // LN2 out
__device__ __nv_bfloat16 g_act_hi[67108864], g_act_lo[67108864];
__device__ float         g_attn[524288];
__device__ __nv_bfloat16 g_qkvT_hi[3145728], g_qkvT_lo[3145728];
__device__ __nv_bfloat16 g_pjT_hi[1048576],  g_pjT_lo[1048576];
__device__ __nv_bfloat16 g_f1T_hi[2097152],  g_f1T_lo[2097152];
__device__ __nv_bfloat16 g_f2T_hi[2097152],  g_f2T_lo[2097152];

// ================= weight transpose + split =================
__global__ __launch_bounds__(256) void trans_split_kernel(
    const float* __restrict__ w, __nv_bfloat16* __restrict__ whi,
    __nv_bfloat16* __restrict__ wlo, int K, int N)
{
    __shared__ float t[32][33];
    int n0 = blockIdx.x * 32, k0 = blockIdx.y * 32;
    int tx = threadIdx.x & 31, ty = threadIdx.x >> 5;
    #pragma unroll
    for (int i = 0; i < 32; i += 8)
        t[ty + i][tx] = w[(size_t)(k0 + ty + i) * N + n0 + tx];
    __syncthreads();
    #pragma unroll
    for (int i = 0; i < 32; i += 8) {
        float v = t[tx][ty + i];
        __nv_bfloat16 hi, lo; split_bf16(v, hi, lo);
        size_t idx = (size_t)(n0 + ty + i) * K + k0 + tx;
        whi[idx] = hi; wlo[idx] = lo;
    }
}

// ================= LayerNorm (fused bf16 split output) =================
__global__ __launch_bounds__(256) void ln_split_kernel(
    const float* __restrict__ x, const float* __restrict__ g, const float* __restrict__ b,
    __nv_bfloat16* __restrict__ yhi, __nv_bfloat16* __restrict__ ylo)
{
    int row = blockIdx.x;
    const float4* xr = reinterpret_cast<const float4*>(x) + (size_t)row * 256;
    float4 v = xr[threadIdx.x];
    float s  = v.x + v.y + v.z + v.w;
    float s2 = v.x*v.x + v.y*v.y + v.z*v.z + v.w*v.w;
    #pragma unroll
    for (int o = 16; o; o >>= 1) {
        s  += __shfl_down_sync(0xffffffffu, s,  o);
        s2 += __shfl_down_sync(0xffffffffu, s2, o);
    }
    __shared__ float ss[8], ss2[8];
    int w = threadIdx.x >> 5, l = threadIdx.x & 31;
    if (l == 0) { ss[w] = s; ss2[w] = s2; }
    __syncthreads();
    if (threadIdx.x == 0) {
        float t = 0.f, t2 = 0.f;
        #pragma unroll
        for (int i = 0; i < 8; i++) { t += ss[i]; t2 += ss2[i]; }
        ss[0] = t; ss2[0] = t2;
    }
    __syncthreads();
    float mean = ss[0] * (1.0f / 1024.0f);
    float var  = ss2[0] * (1.0f / 1024.0f) - mean * mean;
    float rstd = rsqrtf(var + 1e-5f);
    const float4 gv = reinterpret_cast<const float4*>(g)[threadIdx.x];
    const float4 bv = reinterpret_cast<const float4*>(b)[threadIdx.x];
    float o0 = (v.x - mean) * rstd * gv.x + bv.x;
    float o1 = (v.y - mean) * rstd * gv.y + bv.y;
    float o2 = (v.z - mean) * rstd * gv.z + bv.z;
    float o3 = (v.w - mean) * rstd * gv.w + bv.w;
    __nv_bfloat16 h0,l0,h1,l1,h2,l2,h3,l3;
    split_bf16(o0,h0,l0); split_bf16(o1,h1,l1); split_bf16(o2,h2,l2); split_bf16(o3,h3,l3);
    size_t base = (size_t)row * 1024 + threadIdx.x * 4;
    __nv_bfloat162 p;
    p.x=h0; p.y=h1; *reinterpret_cast<__nv_bfloat162*>(yhi+base)   = p;
    p.x=h2; p.y=h3; *reinterpret_cast<__nv_bfloat162*>(yhi+base+2) = p;
    p.x=l0; p.y=l1; *reinterpret_cast<__nv_bfloat162*>(ylo+base)   = p;
    p.x=l2; p.y=l3; *reinterpret_cast<__nv_bfloat162*>(ylo+base+2) = p;
}

// ================= cg2 tcgen05 split-bf16 GEMM, pair tile 256x256, BK=64 =================
// Cluster (2,1,1): CTA pair covers M rows [bx0*128, bx0*128+256). Each CTA loads its own
// A half (128 rows) and its own B half (N/2 = 128 rows). Leader (rank 0) issues cg2 MMAs.
static constexpr int BK = 64;
static constexpr uint32_t IDESC_CG2 =
    (1u << 4) | (1u << 7) | (1u << 10) | ((256 / 8) << 17) | ((256 / 16) << 24);
static constexpr int SMEM_HT = 128 * 128;                 // 16 KB per half-tile (hi or lo)
static constexpr int SMEM_STAGE = 4 * SMEM_HT;            // 64 KB: AH, AL, BH, BL
static constexpr int SMEM_T0 = 1024;
static constexpr int SMEM_BYTES_TOTAL = SMEM_T0 + 2 * SMEM_STAGE;  // 132096

__device__ __forceinline__ void load_half_async(
    const __nv_bfloat16* __restrict__ src, int row0, int K, int kofs,
    uint32_t sdst, int tid)
{
    #pragma unroll
    for (int i = 0; i < 4; ++i) {              // 128 rows * 8 chunks / 256 threads
        int idx = tid + i * 256;
        int r = idx >> 3, c = idx & 7;
        const __nv_bfloat16* g = src + (size_t)(row0 + r) * K + kofs + c * 8;
        uint32_t a = sdst + SMEM_SWIZZLE_128B(r * 128 + c * 16);
        CP_ASYNC16(a, g);
    }
}

template<int EPI>
__global__ __launch_bounds__(256, 1) __cluster_dims__(2, 1, 1) void tgemm_kernel(
    const __nv_bfloat16* __restrict__ Ahi, const __nv_bfloat16* __restrict__ Alo,
    const __nv_bfloat16* __restrict__ Bhi, const __nv_bfloat16* __restrict__ Blo,
    const float* __restrict__ bias, const float* __restrict__ res,
    float* __restrict__ Cout, __nv_bfloat16* __restrict__ Chi, __nv_bfloat16* __restrict__ Clo,
    int M, int N, int K)
{
#if TCOK
    extern __shared__ char smem[];
    const uint32_t sb = smem_to_u32(smem);
    const int tid = threadIdx.x;
    const int wid = tid >> 5, lid = tid & 31;
    const uint32_t rank = cluster_rank();
    const int m0 = blockIdx.x * 128;                 // this CTA's A half
    const int n0 = blockIdx.y * 256;                 // pair's N tile
    const int nb0 = n0 + (int)rank * 128;            // this CTA's B half
    const int NK = K / BK;
    const uint32_t done0 = sb + 16, done1 = sb + 24;

    if (wid == 0) TCGEN05_ALLOC_CG2(sb, 256);
    if (tid == 0) { MBARRIER_INIT(done0, 1); MBARRIER_INIT(done1, 1); }
    __syncthreads();
    uint32_t tmem;
    asm volatile("ld.shared.b32 %0, [%1];" : "=r"(tmem) : "r"(sb));

    // prologue: fill stage 0 with chunk 0 (own halves)
    {
        uint32_t tb = sb + SMEM_T0;
        load_half_async(Ahi, m0,  K, 0, tb,               tid);
        load_half_async(Alo, m0,  K, 0, tb + SMEM_HT,     tid);
        load_half_async(Bhi, nb0, K, 0, tb + 2 * SMEM_HT, tid);
        load_half_async(Blo, nb0, K, 0, tb + 3 * SMEM_HT, tid);
        CP_COMMIT(); CP_WAIT0();
    }
    FENCE_PROXY();
    __syncthreads();
    CLUSTER_SYNC();   // mbarrier init + stage0 data visible cluster-wide

    int ph0 = 0, ph1 = 0;
    for (int kt = 0; kt < NK; ++kt) {
        const int s = kt & 1;
        const uint32_t tb = sb + SMEM_T0 + s * SMEM_STAGE;
        if (rank == 0 && wid == 0) {
            uint64_t dAh = MAKE_SMEM_DESC(tb);
            uint64_t dAl = MAKE_SMEM_DESC(tb + SMEM_HT);
            uint64_t dBh = MAKE_SMEM_DESC(tb + 2 * SMEM_HT);
            uint64_t dBl = MAKE_SMEM_DESC(tb + 3 * SMEM_HT);
            if (elect_one_pred()) {
                #pragma unroll
                for (int st = 0; st < 4; ++st) {
                    mma_f16_ss_cg2(tmem, dAh + st * 2, dBh + st * 2, IDESC_CG2, !(kt == 0 && st == 0));
                    mma_f16_ss_cg2(tmem, dAh + st * 2, dBl + st * 2, IDESC_CG2, true);
                    mma_f16_ss_cg2(tmem, dAl + st * 2, dBh + st * 2, IDESC_CG2, true);
                }
                TCGEN05_COMMIT_MC2(s ? done1 : done0);
            }
        }
        if (kt + 1 < NK) {
            if (kt >= 1) {   // stage 1-s was read by MMA kt-1 (both CTAs' smem) — wait for its commit
                if (s) { MBARRIER_WAIT_PARITY(done0, ph0); ph0 ^= 1; }
                else   { MBARRIER_WAIT_PARITY(done1, ph1); ph1 ^= 1; }
            }
            const uint32_t nb = sb + SMEM_T0 + (1 - s) * SMEM_STAGE;
            const int ko = (kt + 1) * BK;
            load_half_async(Ahi, m0,  K, ko, nb,               tid);
            load_half_async(Alo, m0,  K, ko, nb + SMEM_HT,     tid);
            load_half_async(Bhi, nb0, K, ko, nb + 2 * SMEM_HT, tid);
            load_half_async(Blo, nb0, K, ko, nb + 3 * SMEM_HT, tid);
            CP_COMMIT(); CP_WAIT0();   // MMA kt runs on the tensor pipe meanwhile
            FENCE_PROXY();
            CLUSTER_SYNC();            // both CTAs' next-stage data ready before MMA kt+1
        }
    }

    // wait for the final chunk's commit (covers all MMAs)
    if ((NK - 1) & 1) { MBARRIER_WAIT_PARITY(done1, ph1); }
    else              { MBARRIER_WAIT_PARITY(done0, ph0); }
    TCGEN05_FENCE_AFTER();

    // Epilogue: this CTA owns its 128 rows of D, 256 cols in own TMEM.
    // warps 0-3 -> cols [0,128), warps 4-7 -> cols [128,256)
    const int colgrp = (wid >> 2) * 128;
    const int row = m0 + (wid & 3) * 32 + lid;
    #pragma unroll
    for (int g4 = 0; g4 < 4; ++g4) {
        uint32_t dr[32];
        TCGEN05_LD_32X32B_X32(dr, tmem + colgrp + g4 * 32);
        TCGEN05_WAIT_LD();
        const int ncol0 = n0 + colgrp + g4 * 32;
        const size_t rowoff = (size_t)row * N + ncol0;
        #pragma unroll
        for (int j = 0; j < 32; j += 4) {
            float c[4];
            #pragma unroll
            for (int u = 0; u < 4; ++u) {
                float t = __uint_as_float(dr[j + u]);
                if (EPI >= 2) t += bias[ncol0 + j + u];
                if (EPI == 2) t += res[rowoff + j + u];
                if (EPI == 3) t = gelu_exact(t);
                c[u] = t;
            }
            if (EPI != 3) {
                *reinterpret_cast<float4*>(&Cout[rowoff + j]) = make_float4(c[0], c[1], c[2], c[3]);
            } else {
                __nv_bfloat16 h[4], l[4];
                #pragma unroll
                for (int u = 0; u < 4; ++u) split_bf16(c[u], h[u], l[u]);
                __nv_bfloat162 p;
                p.x=h[0]; p.y=h[1]; *reinterpret_cast<__nv_bfloat162*>(Chi + rowoff + j)     = p;
                p.x=h[2]; p.y=h[3]; *reinterpret_cast<__nv_bfloat162*>(Chi + rowoff + j + 2) = p;
                p.x=l[0]; p.y=l[1]; *reinterpret_cast<__nv_bfloat162*>(Clo + rowoff + j)     = p;
                p.x=l[2]; p.y=l[3]; *reinterpret_cast<__nv_bfloat162*>(Clo + rowoff + j + 2) = p;
            }
        }
    }
    __syncthreads();
    if (wid == 0) { TCGEN05_RELINQUISH_CG2(); TCGEN05_DEALLOC_CG2(tmem, 256); }
    CLUSTER_SYNC();   // no CTA exits while its smem/TMEM may be referenced by the pair
#endif  // TCOK
}

// ================= attention scores + softmax (QKV packed, stride 3072) =================
__global__ __launch_bounds__(256) void scores_kernel(const float* __restrict__ QKV,
                                                     float* __restrict__ attn)
{
    int bh = blockIdx.x;
    int b = bh >> 4, h = bh & 15;
    __shared__ float qs[32][64];
    __shared__ float ks[32][64];
    __shared__ float Ssm[64][65];
    int tid = threadIdx.x;
    int d0 = (tid & 15) * 4;
    int e0 = (tid >> 4) * 4;
    float acc[4][4] = {};
    size_t base = (size_t)b * N_SEQ * QKV_STRIDE + h * 64;

    for (int n0 = 0; n0 < N_SEQ; n0 += 32) {
        #pragma unroll
        for (int i = 0; i < 2; i++) {
            int f  = tid + i * 256;
            int nn = f >> 4;
            int dd = (f & 15) * 4;
            size_t src = base + (size_t)(n0 + nn) * QKV_STRIDE + dd;
            float4 qv = *reinterpret_cast<const float4*>(&QKV[src]);
            float4 kv = *reinterpret_cast<const float4*>(&QKV[src + 1024]);
            *reinterpret_cast<float4*>(&qs[nn][dd]) = qv;
            *reinterpret_cast<float4*>(&ks[nn][dd]) = kv;
        }
        __syncthreads();
        #pragma unroll 4
        for (int nn = 0; nn < 32; nn++) {
            float4 qv = *reinterpret_cast<const float4*>(&qs[nn][d0]);
            float4 kv = *reinterpret_cast<const float4*>(&ks[nn][e0]);
            float a[4] = {qv.x, qv.y, qv.z, qv.w};
            float c[4] = {kv.x, kv.y, kv.z, kv.w};
            #pragma unroll
            for (int i = 0; i < 4; i++)
                #pragma unroll
                for (int j = 0; j < 4; j++)
                    acc[i][j] = fmaf(a[i], c[j], acc[i][j]);
        }
        __syncthreads();
    }
    #pragma unroll
    for (int i = 0; i < 4; i++)
        #pragma unroll
        for (int j = 0; j < 4; j++)
            Ssm[d0 + i][e0 + j] = acc[i][j] * 0.125f;
    __syncthreads();

    if (tid < 64) {
        float mx = -1e30f;
        #pragma unroll 8
        for (int e = 0; e < 64; e++) mx = fmaxf(mx, Ssm[tid][e]);
        float sum = 0.f;
        #pragma unroll 8
        for (int e = 0; e < 64; e++) {
            float p = __expf(Ssm[tid][e] - mx);
            Ssm[tid][e] = p;
            sum += p;
        }
        float inv = 1.0f / sum;
        size_t dst = ((size_t)bh * 64 + tid) * 64;
        #pragma unroll 8
        for (int e = 0; e < 64; e++) attn[dst + e] = Ssm[tid][e] * inv;
    }
}

// ================= o = attn @ v with fused (0,2,1,3) permute + bf16 split out =================
__global__ __launch_bounds__(256) void av_kernel(const float* __restrict__ attn,
                                                 const float* __restrict__ QKV,
                                                 __nv_bfloat16* __restrict__ Ohi,
                                                 __nv_bfloat16* __restrict__ Olo)
{
    int bh = blockIdx.x;
    int b = bh >> 4, h = bh & 15;
    int n0 = blockIdx.y * 64;
    __shared__ float at[64][68];
    __shared__ float vs[64][68];
    int tid = threadIdx.x;

    const float4* ap = reinterpret_cast<const float4*>(attn + (size_t)bh * 4096);
    #pragma unroll
    for (int i = 0; i < 4; i++) {
        int f = tid + i * 256;
        int d = f >> 4, e4 = (f & 15) * 4;
        float4 a = ap[f];
        at[e4+0][d] = a.x; at[e4+1][d] = a.y; at[e4+2][d] = a.z; at[e4+3][d] = a.w;
    }
    size_t vbase = ((size_t)b * N_SEQ + n0) * QKV_STRIDE + h * 64 + 2048;
    #pragma unroll
    for (int i = 0; i < 4; i++) {
        int f = tid + i * 256;
        int nn = f >> 4, e4 = (f & 15) * 4;
        float4 vv = *reinterpret_cast<const float4*>(&QKV[vbase + (size_t)nn * QKV_STRIDE + e4]);
        vs[e4+0][nn] = vv.x; vs[e4+1][nn] = vv.y; vs[e4+2][nn] = vv.z; vs[e4+3][nn] = vv.w;
    }
    __syncthreads();

    int nn0 = (tid & 15) * 4;
    int d0  = (tid >> 4) * 4;
    float acc[4][4] = {};
    #pragma unroll 8
    for (int e = 0; e < 64; e++) {
        float4 av = *reinterpret_cast<const float4*>(&at[e][d0]);
        float4 vv = *reinterpret_cast<const float4*>(&vs[e][nn0]);
        float a[4] = {av.x, av.y, av.z, av.w};
        float v4[4] = {vv.x, vv.y, vv.z, vv.w};
        #pragma unroll
        for (int i = 0; i < 4; i++)
            #pragma unroll
            for (int j = 0; j < 4; j++)
                acc[i][j] = fmaf(a[i], v4[j], acc[i][j]);
    }

    int nblk = n0 >> 10;
    int ncol = n0 & 1023;
    #pragma unroll
    for (int i = 0; i < 4; i++) {
        int d = d0 + i;
        size_t row = (size_t)b * N_SEQ + (size_t)(d * 16 + h) * 4 + nblk;
        size_t off = row * C_DIM + ncol + nn0;
        __nv_bfloat16 hh[4], ll[4];
        #pragma unroll
        for (int j = 0; j < 4; j++) split_bf16(acc[i][j], hh[j], ll[j]);
        __nv_bfloat162 p;
        p.x=hh[0]; p.y=hh[1]; *reinterpret_cast<__nv_bfloat162*>(Ohi + off)     = p;
        p.x=hh[2]; p.y=hh[3]; *reinterpret_cast<__nv_bfloat162*>(Ohi + off + 2) = p;
        p.x=ll[0]; p.y=ll[1]; *reinterpret_cast<__nv_bfloat162*>(Olo + off)     = p;
        p.x=ll[2]; p.y=ll[3]; *reinterpret_cast<__nv_bfloat162*>(Olo + off + 2) = p;
    }
}

// ================= host launch =================
extern "C" void kernel_launch(void* const* d_in, const int* in_sizes, int n_in,
                              void* d_out, int out_size)
{
    const float* x      = (const float*)d_in[0];
    const float* ln1_g  = (const float*)d_in[1];
    const float* ln1_b  = (const float*)d_in[2];
    const float* ln2_g  = (const float*)d_in[3];
    const float* ln2_b  = (const float*)d_in[4];
    const float* wq     = (const float*)d_in[5];
    const float* wk     = (const float*)d_in[6];
    const float* wv     = (const float*)d_in[7];
    const float* proj_w = (const float*)d_in[8];
    const float* proj_b = (const float*)d_in[9];
    const float* fc1_w  = (const float*)d_in[10];
    const float* fc1_b  = (const float*)d_in[11];
    const float* fc2_w  = (const float*)d_in[12];
    const float* fc2_b  = (const float*)d_in[13];
    float* out = (float*)d_out;

    __nv_bfloat16 *h_hi,*h_lo,*o_hi,*o_lo,*h2_hi,*h2_lo,*act_hi,*act_lo;
    __nv_bfloat16 *qkvT_hi,*qkvT_lo,*pjT_hi,*pjT_lo,*f1T_hi,*f1T_lo,*f2T_hi,*f2T_lo;
    float *qkv,*x1,*attn;
    cudaGetSymbolAddress((void**)&h_hi,  g_h_hi);   cudaGetSymbolAddress((void**)&h_lo,  g_h_lo);
    cudaGetSymbolAddress((void**)&o_hi,  g_o_hi);   cudaGetSymbolAddress((void**)&o_lo,  g_o_lo);
    cudaGetSymbolAddress((void**)&h2_hi, g_h2_hi);  cudaGetSymbolAddress((void**)&h2_lo, g_h2_lo);
    cudaGetSymbolAddress((void**)&act_hi,g_act_hi); cudaGetSymbolAddress((void**)&act_lo,g_act_lo);
    cudaGetSymbolAddress((void**)&qkv, g_qkv);      cudaGetSymbolAddress((void**)&x1,  g_x1);
    cudaGetSymbolAddress((void**)&attn, g_attn);
    cudaGetSymbolAddress((void**)&qkvT_hi, g_qkvT_hi); cudaGetSymbolAddress((void**)&qkvT_lo, g_qkvT_lo);
    cudaGetSymbolAddress((void**)&pjT_hi,  g_pjT_hi);  cudaGetSymbolAddress((void**)&pjT_lo,  g_pjT_lo);
    cudaGetSymbolAddress((void**)&f1T_hi,  g_f1T_hi);  cudaGetSymbolAddress((void**)&f1T_lo,  g_f1T_lo);
    cudaGetSymbolAddress((void**)&f2T_hi,  g_f2T_hi);  cudaGetSymbolAddress((void**)&f2T_lo,  g_f2T_lo);

    cudaFuncSetAttribute(tgemm_kernel<0>, cudaFuncAttributeMaxDynamicSharedMemorySize, SMEM_BYTES_TOTAL);
    cudaFuncSetAttribute(tgemm_kernel<2>, cudaFuncAttributeMaxDynamicSharedMemorySize, SMEM_BYTES_TOTAL);
    cudaFuncSetAttribute(tgemm_kernel<3>, cudaFuncAttributeMaxDynamicSharedMemorySize, SMEM_BYTES_TOTAL);

    // weight prep (attention block first)
    trans_split_kernel<<<dim3(32,32),256>>>(wq,     qkvT_hi,               qkvT_lo,               1024, 1024);
    trans_split_kernel<<<dim3(32,32),256>>>(wk,     qkvT_hi + 1024 * 1024, qkvT_lo + 1024 * 1024, 1024, 1024);
    trans_split_kernel<<<dim3(32,32),256>>>(wv,     qkvT_hi + 2048 * 1024, qkvT_lo + 2048 * 1024, 1024, 1024);
    trans_split_kernel<<<dim3(32,32),256>>>(proj_w, pjT_hi,                pjT_lo,                1024, 1024);
    // LN1
    ln_split_kernel<<<M_ROWS, 256>>>(x, ln1_g, ln1_b, h_hi, h_lo);
    // fused QKV GEMM (cluster pairs along x)
    tgemm_kernel<0><<<dim3(M_ROWS / 128, QKV_STRIDE / 256), 256, SMEM_BYTES_TOTAL>>>(
        h_hi, h_lo, qkvT_hi, qkvT_lo, nullptr, nullptr, qkv, nullptr, nullptr, M_ROWS, QKV_STRIDE, C_DIM);
    // attention
    scores_kernel<<<128, 256>>>(qkv, attn);
    av_kernel<<<dim3(128, 64), 256>>>(attn, qkv, o_hi, o_lo);
    // MLP weight prep
    trans_split_kernel<<<dim3(64,32),256>>>(fc1_w,  f1T_hi, f1T_lo, 1024, 2048);
    trans_split_kernel<<<dim3(32,64),256>>>(fc2_w,  f2T_hi, f2T_lo, 2048, 1024);
    // proj + bias + residual -> x1
    tgemm_kernel<2><<<dim3(M_ROWS / 128, C_DIM / 256), 256, SMEM_BYTES_TOTAL>>>(
        o_hi, o_lo, pjT_hi, pjT_lo, proj_b, x, x1, nullptr, nullptr, M_ROWS, C_DIM, C_DIM);
    // LN2
    ln_split_kernel<<<M_ROWS, 256>>>(x1, ln2_g, ln2_b, h2_hi, h2_lo);
    // FC1 + bias + gelu
    tgemm_kernel<3><<<dim3(M_ROWS / 128, HF_DIM / 256), 256, SMEM_BYTES_TOTAL>>>(
        h2_hi, h2_lo, f1T_hi, f1T_lo, fc1_b, nullptr, nullptr, act_hi, act_lo, M_ROWS, HF_DIM, C_DIM);
    // FC2 + bias + residual
    tgemm_kernel<2><<<dim3(M_ROWS / 128, C_DIM / 256), 256, SMEM_BYTES_TOTAL>>>(
        act_hi, act_lo, f2T_hi, f2T_lo, fc2_b, x1, out, nullptr, nullptr, M_ROWS, C_DIM, HF_DIM);
}

// round 7
// speedup vs baseline: 1.2459x; 1.2459x over previous
#include <cuda_runtime.h>
#include <cuda.h>
#include <cuda_bf16.h>
#include <cstdint>

// B=8, N=4096, C=1024, H=16, d=64, Hf=2048; M = B*N = 32768 rows.
#define M_ROWS 32768
#define C_DIM  1024
#define HF_DIM 2048
#define N_SEQ  4096
#define QKV_STRIDE 3072

// tcgen05 is arch-specific ("a"-target) only; hide from plain compute_103 pass.
#if defined(__CUDA_ARCH_FEAT_SM103_ALL) || defined(__CUDA_ARCH_FEAT_SM100_ALL) || defined(__CUDA_ARCH_SPECIFIC__)
#define TCOK 1
#else
#define TCOK 0
#endif

// ================= PTX helpers =================
__device__ __forceinline__ uint32_t smem_to_u32(const void* p) {
    uint32_t a;
    asm("{ .reg .u64 t; cvta.to.shared.u64 t, %1; cvt.u32.u64 %0, t; }" : "=r"(a) : "l"(p));
    return a;
}
__device__ __forceinline__ uint32_t elect_one_pred() {
    uint32_t p;
    asm volatile("{\n\t.reg .pred p;\n\telect.sync _|p, 0xFFFFFFFF;\n\tselp.b32 %0, 1, 0, p;\n\t}" : "=r"(p));
    return p;
}
#define MBARRIER_INIT(addr, cnt) \
    asm volatile("mbarrier.init.shared.b64 [%0], %1;" :: "r"((uint32_t)(addr)), "r"((uint32_t)(cnt)) : "memory")
#define MBARRIER_EXPECT_TX(addr, bytes) \
    asm volatile("mbarrier.arrive.expect_tx.shared.b64 _, [%0], %1;" :: "r"((uint32_t)(addr)), "r"((uint32_t)(bytes)) : "memory")
#define MBARRIER_WAIT_PARITY(mbar_smem_addr, phase_parity) do { \
    uint32_t _mbar = (uint32_t)(mbar_smem_addr); \
    uint32_t _parity = (uint32_t)(phase_parity); \
    uint32_t _done; \
    asm volatile("{\n\t.reg .pred p;\n\tmbarrier.try_wait.parity.acquire.cta.shared::cta.b64 p, [%1], %2;\n\tselp.b32 %0, 1, 0, p;\n\t}" \
        : "=r"(_done) : "r"(_mbar), "r"(_parity) : "memory"); \
    if (!_done) { \
        asm volatile("{\n\t.reg .pred P1;\n\tWAIT_LOOP_%=:\n\tmbarrier.try_wait.parity.acquire.cta.shared::cta.b64 P1, [%0], %1, 0x989680;\n\t@P1 bra.uni WAIT_DONE_%=;\n\tbra.uni WAIT_LOOP_%=;\n\tWAIT_DONE_%=:\n\t}" \
            :: "r"(_mbar), "r"(_parity) : "memory"); \
    } \
} while(0)
#define FENCE_PROXY() asm volatile("fence.proxy.async.shared::cta;" ::: "memory")
#define TMA_2D(smem, tmap, cx, cy, mbar) \
    asm volatile("cp.async.bulk.tensor.2d.shared::cta.global.tile.mbarrier::complete_tx::bytes [%0], [%1, {%2, %3}], [%4];" \
        :: "r"((uint32_t)(smem)), "l"(tmap), "r"((int)(cx)), "r"((int)(cy)), "r"((uint32_t)(mbar)) : "memory")

#if TCOK
#define TCGEN05_ALLOC(smem_addr, nCols) \
    asm volatile("tcgen05.alloc.cta_group::1.sync.aligned.shared::cta.b32 [%0], %1;" \
        :: "r"((uint32_t)(smem_addr)), "r"((uint32_t)(nCols)) : "memory")
#define TCGEN05_DEALLOC(tmem_addr, nCols) \
    asm volatile("tcgen05.dealloc.cta_group::1.sync.aligned.b32 %0, %1;" :: "r"(tmem_addr), "r"((uint32_t)(nCols)))
#define TCGEN05_RELINQUISH() \
    asm volatile("tcgen05.relinquish_alloc_permit.cta_group::1.sync.aligned;")
#define TCGEN05_COMMIT(mbar) \
    asm volatile("tcgen05.commit.cta_group::1.mbarrier::arrive::one.shared::cluster.b64 [%0];" \
        :: "r"((uint32_t)(mbar)) : "memory")
#define TCGEN05_WAIT_LD()  asm volatile("tcgen05.wait::ld.sync.aligned;" ::: "memory")
#define TCGEN05_FENCE_AFTER()  asm volatile("tcgen05.fence::after_thread_sync;" ::: "memory")
#define TCGEN05_LD_32X32B_X32(r, tmem_addr) \
    asm volatile("tcgen05.ld.sync.aligned.32x32b.x32.b32 " \
        "{%0, %1, %2, %3, %4, %5, %6, %7, %8, %9, %10, %11, %12, %13, %14, %15, " \
        " %16, %17, %18, %19, %20, %21, %22, %23, %24, %25, %26, %27, %28, %29, %30, %31}, [%32];" \
        : "=r"((r)[0]),  "=r"((r)[1]),  "=r"((r)[2]),  "=r"((r)[3]), \
          "=r"((r)[4]),  "=r"((r)[5]),  "=r"((r)[6]),  "=r"((r)[7]), \
          "=r"((r)[8]),  "=r"((r)[9]),  "=r"((r)[10]), "=r"((r)[11]), \
          "=r"((r)[12]), "=r"((r)[13]), "=r"((r)[14]), "=r"((r)[15]), \
          "=r"((r)[16]), "=r"((r)[17]), "=r"((r)[18]), "=r"((r)[19]), \
          "=r"((r)[20]), "=r"((r)[21]), "=r"((r)[22]), "=r"((r)[23]), \
          "=r"((r)[24]), "=r"((r)[25]), "=r"((r)[26]), "=r"((r)[27]), \
          "=r"((r)[28]), "=r"((r)[29]), "=r"((r)[30]), "=r"((r)[31]) \
        : "r"(tmem_addr))

// SS-mode f16-kind MMA (bf16 inputs, f32 accum), cta_group::1
__device__ __forceinline__ void mma_f16_ss(uint32_t d_tmem, uint64_t a_desc, uint64_t b_desc,
                                           uint32_t idesc, bool accum) {
    uint32_t en = accum ? 1u : 0u;
    asm volatile(
        "{\n\t.reg .pred p;\n\tsetp.ne.u32 p, %5, 0;\n\t"
        "tcgen05.mma.cta_group::1.kind::f16 [%0], %1, %2, %3, {%4, %4, %4, %4}, p;\n\t}"
        :: "r"(d_tmem), "l"(a_desc), "l"(b_desc), "r"(idesc), "r"(0u), "r"(en)
        : "memory");
}
#endif  // TCOK

static constexpr uint64_t SMEM_DESC_BASE_SW128 =
    (uint64_t(2) << 61) | (uint64_t(1) << 46) | (uint64_t(64) << 32) | (uint64_t(1) << 16);
#define MAKE_SMEM_DESC(base_addr) (SMEM_DESC_BASE_SW128 | ((uint64_t)((base_addr) >> 4) & 0x3FFF))

__device__ __forceinline__ void split_bf16(float v, __nv_bfloat16& hi, __nv_bfloat16& lo) {
    hi = __float2bfloat16(v);
    lo = __float2bfloat16(v - __bfloat162float(hi));
}
__device__ __forceinline__ float gelu_exact(float x) {
    return 0.5f * x * (1.0f + erff(x * 0.70710678118654752440f));
}

// ================= scratch =================
__device__ __nv_bfloat16 g_h_hi[33554432],  g_h_lo[33554432];     // LN1 out
__device__ float         g_qkv[100663296];                        // Q|K|V  (M, 3072)
__device__ __nv_bfloat16 g_o_hi[33554432],  g_o_lo[33554432];     // attn out (permuted)
__device__ float         g_x1[33554432];
__device__ __nv_bfloat16 g_h2_hi[33554432], g_h2_lo[33554432];    // LN2 out
__device__ __nv_bfloat16 g_act_hi[67108864], g_act_lo[67108864];
__device__ float         g_attn[524288];
__device__ __nv_bfloat16 g_qkvT_hi[3145728], g_qkvT_lo[3145728];
__device__ __nv_bfloat16 g_pjT_hi[1048576],  g_pjT_lo[1048576];
__device__ __nv_bfloat16 g_f1T_hi[2097152],  g_f1T_lo[2097152];
__device__ __nv_bfloat16 g_f2T_hi[2097152],  g_f2T_lo[2097152];

// ================= weight transpose + split =================
__global__ __launch_bounds__(256) void trans_split_kernel(
    const float* __restrict__ w, __nv_bfloat16* __restrict__ whi,
    __nv_bfloat16* __restrict__ wlo, int K, int N)
{
    __shared__ float t[32][33];
    int n0 = blockIdx.x * 32, k0 = blockIdx.y * 32;
    int tx = threadIdx.x & 31, ty = threadIdx.x >> 5;
    #pragma unroll
    for (int i = 0; i < 32; i += 8)
        t[ty + i][tx] = w[(size_t)(k0 + ty + i) * N + n0 + tx];
    __syncthreads();
    #pragma unroll
    for (int i = 0; i < 32; i += 8) {
        float v = t[tx][ty + i];
        __nv_bfloat16 hi, lo; split_bf16(v, hi, lo);
        size_t idx = (size_t)(n0 + ty + i) * K + k0 + tx;
        whi[idx] = hi; wlo[idx] = lo;
    }
}

// ================= LayerNorm (fused bf16 split output) =================
__global__ __launch_bounds__(256) void ln_split_kernel(
    const float* __restrict__ x, const float* __restrict__ g, const float* __restrict__ b,
    __nv_bfloat16* __restrict__ yhi, __nv_bfloat16* __restrict__ ylo)
{
    int row = blockIdx.x;
    const float4* xr = reinterpret_cast<const float4*>(x) + (size_t)row * 256;
    float4 v = xr[threadIdx.x];
    float s  = v.x + v.y + v.z + v.w;
    float s2 = v.x*v.x + v.y*v.y + v.z*v.z + v.w*v.w;
    #pragma unroll
    for (int o = 16; o; o >>= 1) {
        s  += __shfl_down_sync(0xffffffffu, s,  o);
        s2 += __shfl_down_sync(0xffffffffu, s2, o);
    }
    __shared__ float ss[8], ss2[8];
    int w = threadIdx.x >> 5, l = threadIdx.x & 31;
    if (l == 0) { ss[w] = s; ss2[w] = s2; }
    __syncthreads();
    if (threadIdx.x == 0) {
        float t = 0.f, t2 = 0.f;
        #pragma unroll
        for (int i = 0; i < 8; i++) { t += ss[i]; t2 += ss2[i]; }
        ss[0] = t; ss2[0] = t2;
    }
    __syncthreads();
    float mean = ss[0] * (1.0f / 1024.0f);
    float var  = ss2[0] * (1.0f / 1024.0f) - mean * mean;
    float rstd = rsqrtf(var + 1e-5f);
    const float4 gv = reinterpret_cast<const float4*>(g)[threadIdx.x];
    const float4 bv = reinterpret_cast<const float4*>(b)[threadIdx.x];
    float o0 = (v.x - mean) * rstd * gv.x + bv.x;
    float o1 = (v.y - mean) * rstd * gv.y + bv.y;
    float o2 = (v.z - mean) * rstd * gv.z + bv.z;
    float o3 = (v.w - mean) * rstd * gv.w + bv.w;
    __nv_bfloat16 h0,l0,h1,l1,h2,l2,h3,l3;
    split_bf16(o0,h0,l0); split_bf16(o1,h1,l1); split_bf16(o2,h2,l2); split_bf16(o3,h3,l3);
    size_t base = (size_t)row * 1024 + threadIdx.x * 4;
    __nv_bfloat162 p;
    p.x=h0; p.y=h1; *reinterpret_cast<__nv_bfloat162*>(yhi+base)   = p;
    p.x=h2; p.y=h3; *reinterpret_cast<__nv_bfloat162*>(yhi+base+2) = p;
    p.x=l0; p.y=l1; *reinterpret_cast<__nv_bfloat162*>(ylo+base)   = p;
    p.x=l2; p.y=l3; *reinterpret_cast<__nv_bfloat162*>(ylo+base+2) = p;
}

// ================= tcgen05 split-bf16 GEMM, BM=128 x BN=256 x BK=64, TMA fills =================
static constexpr int BM = 128, BN = 256, BK = 64;
static constexpr uint32_t IDESC_BF16 =
    (1u << 4) | (1u << 7) | (1u << 10) | ((BN / 8) << 17) | ((BM / 16) << 24);
static constexpr int SMEM_AT = 128 * 128;            // 16 KB
static constexpr int SMEM_BT = 256 * 128;            // 32 KB
static constexpr int SMEM_STAGE = 2 * SMEM_AT + 2 * SMEM_BT;  // 96 KB
static constexpr uint32_t STAGE_BYTES = (uint32_t)SMEM_STAGE;
static constexpr int SMEM_T0 = 1024;
static constexpr int SMEM_BYTES_TOTAL = SMEM_T0 + 2 * SMEM_STAGE;  // 197632

template<int EPI>
__global__ __launch_bounds__(256, 1) void tgemm_kernel(
    const __grid_constant__ CUtensorMap tAh, const __grid_constant__ CUtensorMap tAl,
    const __grid_constant__ CUtensorMap tBh, const __grid_constant__ CUtensorMap tBl,
    const float* __restrict__ bias, const float* __restrict__ res,
    float* __restrict__ Cout, __nv_bfloat16* __restrict__ Chi, __nv_bfloat16* __restrict__ Clo,
    int M, int N, int K)
{
#if TCOK
    extern __shared__ char smem[];
    const uint32_t sb = smem_to_u32(smem);
    const int tid = threadIdx.x;
    const int wid = tid >> 5, lid = tid & 31;
    const int m0 = blockIdx.y * BM, n0 = blockIdx.x * BN;
    const int NK = K / BK;
    const uint32_t full0 = sb + 16, full1 = sb + 24;
    const uint32_t done0 = sb + 32, done1 = sb + 40;

    if (wid == 0) { TCGEN05_ALLOC(sb, 256); TCGEN05_RELINQUISH(); }
    if (tid == 0) {
        MBARRIER_INIT(full0, 1); MBARRIER_INIT(full1, 1);
        MBARRIER_INIT(done0, 1); MBARRIER_INIT(done1, 1);
        FENCE_PROXY();
    }
    __syncthreads();
    uint32_t tmem;
    asm volatile("ld.shared.b32 %0, [%1];" : "=r"(tmem) : "r"(sb));

    if (tid == 0) {
        const CUtensorMap* pAh = &tAh; const CUtensorMap* pAl = &tAl;
        const CUtensorMap* pBh = &tBh; const CUtensorMap* pBl = &tBl;
        // prologue: TMA both stages
        {
            uint32_t tb = sb + SMEM_T0;
            MBARRIER_EXPECT_TX(full0, STAGE_BYTES);
            TMA_2D(tb,                       pAh, 0, m0, full0);
            TMA_2D(tb + SMEM_AT,             pAl, 0, m0, full0);
            TMA_2D(tb + 2 * SMEM_AT,          pBh, 0, n0, full0);
            TMA_2D(tb + 2 * SMEM_AT + SMEM_BT, pBl, 0, n0, full0);
            uint32_t tb1 = tb + SMEM_STAGE;
            MBARRIER_EXPECT_TX(full1, STAGE_BYTES);
            TMA_2D(tb1,                       pAh, BK, m0, full1);
            TMA_2D(tb1 + SMEM_AT,             pAl, BK, m0, full1);
            TMA_2D(tb1 + 2 * SMEM_AT,          pBh, BK, n0, full1);
            TMA_2D(tb1 + 2 * SMEM_AT + SMEM_BT, pBl, BK, n0, full1);
        }
        int phf0 = 0, phf1 = 0, phd0 = 0, phd1 = 0;
        for (int kt = 0; kt < NK; ++kt) {
            const int s = kt & 1;
            const uint32_t tb = sb + SMEM_T0 + s * SMEM_STAGE;
            if (s) { MBARRIER_WAIT_PARITY(full1, phf1); phf1 ^= 1; }
            else   { MBARRIER_WAIT_PARITY(full0, phf0); phf0 ^= 1; }
            {
                uint64_t dAh = MAKE_SMEM_DESC(tb);
                uint64_t dAl = MAKE_SMEM_DESC(tb + SMEM_AT);
                uint64_t dBh = MAKE_SMEM_DESC(tb + 2 * SMEM_AT);
                uint64_t dBl = MAKE_SMEM_DESC(tb + 2 * SMEM_AT + SMEM_BT);
                #pragma unroll
                for (int st = 0; st < 4; ++st) {
                    mma_f16_ss(tmem, dAh + st * 2, dBh + st * 2, IDESC_BF16, !(kt == 0 && st == 0));
                    mma_f16_ss(tmem, dAh + st * 2, dBl + st * 2, IDESC_BF16, true);
                    mma_f16_ss(tmem, dAl + st * 2, dBh + st * 2, IDESC_BF16, true);
                }
                TCGEN05_COMMIT(s ? done1 : done0);
            }
            if (kt + 2 < NK) {
                // free stage s (wait for the MMAs just issued), then refill with chunk kt+2
                if (s) { MBARRIER_WAIT_PARITY(done1, phd1); phd1 ^= 1; }
                else   { MBARRIER_WAIT_PARITY(done0, phd0); phd0 ^= 1; }
                const int ko = (kt + 2) * BK;
                if (s) { MBARRIER_EXPECT_TX(full1, STAGE_BYTES); }
                else   { MBARRIER_EXPECT_TX(full0, STAGE_BYTES); }
                uint32_t fb = s ? full1 : full0;
                TMA_2D(tb,                       pAh, ko, m0, fb);
                TMA_2D(tb + SMEM_AT,             pAl, ko, m0, fb);
                TMA_2D(tb + 2 * SMEM_AT,          pBh, ko, n0, fb);
                TMA_2D(tb + 2 * SMEM_AT + SMEM_BT, pBl, ko, n0, fb);
            }
        }
        // wait for final commit (covers all MMAs)
        if ((NK - 1) & 1) { MBARRIER_WAIT_PARITY(done1, phd1); }
        else              { MBARRIER_WAIT_PARITY(done0, phd0); }
    }
    __syncthreads();
    TCGEN05_FENCE_AFTER();

    // Epilogue: warps 0-3 -> cols [0,128), warps 4-7 -> cols [128,256)
    const int colgrp = (wid >> 2) * 128;
    const int row = m0 + (wid & 3) * 32 + lid;
    #pragma unroll
    for (int g4 = 0; g4 < 4; ++g4) {
        uint32_t dr[32];
        TCGEN05_LD_32X32B_X32(dr, tmem + colgrp + g4 * 32);
        TCGEN05_WAIT_LD();
        const int ncol0 = n0 + colgrp + g4 * 32;
        const size_t rowoff = (size_t)row * N + ncol0;
        #pragma unroll
        for (int j = 0; j < 32; j += 4) {
            float c[4];
            #pragma unroll
            for (int u = 0; u < 4; ++u) {
                float t = __uint_as_float(dr[j + u]);
                if (EPI >= 2) t += bias[ncol0 + j + u];
                if (EPI == 2) t += res[rowoff + j + u];
                if (EPI == 3) t = gelu_exact(t);
                c[u] = t;
            }
            if (EPI != 3) {
                *reinterpret_cast<float4*>(&Cout[rowoff + j]) = make_float4(c[0], c[1], c[2], c[3]);
            } else {
                __nv_bfloat16 h[4], l[4];
                #pragma unroll
                for (int u = 0; u < 4; ++u) split_bf16(c[u], h[u], l[u]);
                __nv_bfloat162 p;
                p.x=h[0]; p.y=h[1]; *reinterpret_cast<__nv_bfloat162*>(Chi + rowoff + j)     = p;
                p.x=h[2]; p.y=h[3]; *reinterpret_cast<__nv_bfloat162*>(Chi + rowoff + j + 2) = p;
                p.x=l[0]; p.y=l[1]; *reinterpret_cast<__nv_bfloat162*>(Clo + rowoff + j)     = p;
                p.x=l[2]; p.y=l[3]; *reinterpret_cast<__nv_bfloat162*>(Clo + rowoff + j + 2) = p;
            }
        }
    }
    __syncthreads();
    if (wid == 0) { TCGEN05_DEALLOC(tmem, 256); }
#endif  // TCOK
}

// ================= attention scores + softmax (QKV packed, stride 3072) =================
__global__ __launch_bounds__(256) void scores_kernel(const float* __restrict__ QKV,
                                                     float* __restrict__ attn)
{
    int bh = blockIdx.x;
    int b = bh >> 4, h = bh & 15;
    __shared__ float qs[32][64];
    __shared__ float ks[32][64];
    __shared__ float Ssm[64][65];
    int tid = threadIdx.x;
    int d0 = (tid & 15) * 4;
    int e0 = (tid >> 4) * 4;
    float acc[4][4] = {};
    size_t base = (size_t)b * N_SEQ * QKV_STRIDE + h * 64;

    for (int n0 = 0; n0 < N_SEQ; n0 += 32) {
        #pragma unroll
        for (int i = 0; i < 2; i++) {
            int f  = tid + i * 256;
            int nn = f >> 4;
            int dd = (f & 15) * 4;
            size_t src = base + (size_t)(n0 + nn) * QKV_STRIDE + dd;
            float4 qv = *reinterpret_cast<const float4*>(&QKV[src]);
            float4 kv = *reinterpret_cast<const float4*>(&QKV[src + 1024]);
            *reinterpret_cast<float4*>(&qs[nn][dd]) = qv;
            *reinterpret_cast<float4*>(&ks[nn][dd]) = kv;
        }
        __syncthreads();
        #pragma unroll 4
        for (int nn = 0; nn < 32; nn++) {
            float4 qv = *reinterpret_cast<const float4*>(&qs[nn][d0]);
            float4 kv = *reinterpret_cast<const float4*>(&ks[nn][e0]);
            float a[4] = {qv.x, qv.y, qv.z, qv.w};
            float c[4] = {kv.x, kv.y, kv.z, kv.w};
            #pragma unroll
            for (int i = 0; i < 4; i++)
                #pragma unroll
                for (int j = 0; j < 4; j++)
                    acc[i][j] = fmaf(a[i], c[j], acc[i][j]);
        }
        __syncthreads();
    }
    #pragma unroll
    for (int i = 0; i < 4; i++)
        #pragma unroll
        for (int j = 0; j < 4; j++)
            Ssm[d0 + i][e0 + j] = acc[i][j] * 0.125f;
    __syncthreads();

    if (tid < 64) {
        float mx = -1e30f;
        #pragma unroll 8
        for (int e = 0; e < 64; e++) mx = fmaxf(mx, Ssm[tid][e]);
        float sum = 0.f;
        #pragma unroll 8
        for (int e = 0; e < 64; e++) {
            float p = __expf(Ssm[tid][e] - mx);
            Ssm[tid][e] = p;
            sum += p;
        }
        float inv = 1.0f / sum;
        size_t dst = ((size_t)bh * 64 + tid) * 64;
        #pragma unroll 8
        for (int e = 0; e < 64; e++) attn[dst + e] = Ssm[tid][e] * inv;
    }
}

// ================= o = attn @ v with fused (0,2,1,3) permute + bf16 split out =================
__global__ __launch_bounds__(256) void av_kernel(const float* __restrict__ attn,
                                                 const float* __restrict__ QKV,
                                                 __nv_bfloat16* __restrict__ Ohi,
                                                 __nv_bfloat16* __restrict__ Olo)
{
    int bh = blockIdx.x;
    int b = bh >> 4, h = bh & 15;
    int n0 = blockIdx.y * 64;
    __shared__ float at[64][68];
    __shared__ float vs[64][68];
    int tid = threadIdx.x;

    const float4* ap = reinterpret_cast<const float4*>(attn + (size_t)bh * 4096);
    #pragma unroll
    for (int i = 0; i < 4; i++) {
        int f = tid + i * 256;
        int d = f >> 4, e4 = (f & 15) * 4;
        float4 a = ap[f];
        at[e4+0][d] = a.x; at[e4+1][d] = a.y; at[e4+2][d] = a.z; at[e4+3][d] = a.w;
    }
    size_t vbase = ((size_t)b * N_SEQ + n0) * QKV_STRIDE + h * 64 + 2048;
    #pragma unroll
    for (int i = 0; i < 4; i++) {
        int f = tid + i * 256;
        int nn = f >> 4, e4 = (f & 15) * 4;
        float4 vv = *reinterpret_cast<const float4*>(&QKV[vbase + (size_t)nn * QKV_STRIDE + e4]);
        vs[e4+0][nn] = vv.x; vs[e4+1][nn] = vv.y; vs[e4+2][nn] = vv.z; vs[e4+3][nn] = vv.w;
    }
    __syncthreads();

    int nn0 = (tid & 15) * 4;
    int d0  = (tid >> 4) * 4;
    float acc[4][4] = {};
    #pragma unroll 8
    for (int e = 0; e < 64; e++) {
        float4 av = *reinterpret_cast<const float4*>(&at[e][d0]);
        float4 vv = *reinterpret_cast<const float4*>(&vs[e][nn0]);
        float a[4] = {av.x, av.y, av.z, av.w};
        float v4[4] = {vv.x, vv.y, vv.z, vv.w};
        #pragma unroll
        for (int i = 0; i < 4; i++)
            #pragma unroll
            for (int j = 0; j < 4; j++)
                acc[i][j] = fmaf(a[i], v4[j], acc[i][j]);
    }

    int nblk = n0 >> 10;
    int ncol = n0 & 1023;
    #pragma unroll
    for (int i = 0; i < 4; i++) {
        int d = d0 + i;
        size_t row = (size_t)b * N_SEQ + (size_t)(d * 16 + h) * 4 + nblk;
        size_t off = row * C_DIM + ncol + nn0;
        __nv_bfloat16 hh[4], ll[4];
        #pragma unroll
        for (int j = 0; j < 4; j++) split_bf16(acc[i][j], hh[j], ll[j]);
        __nv_bfloat162 p;
        p.x=hh[0]; p.y=hh[1]; *reinterpret_cast<__nv_bfloat162*>(Ohi + off)     = p;
        p.x=hh[2]; p.y=hh[3]; *reinterpret_cast<__nv_bfloat162*>(Ohi + off + 2) = p;
        p.x=ll[0]; p.y=ll[1]; *reinterpret_cast<__nv_bfloat162*>(Olo + off)     = p;
        p.x=ll[2]; p.y=ll[3]; *reinterpret_cast<__nv_bfloat162*>(Olo + off + 2) = p;
    }
}

// ================= host: tensormap encode via driver entry point =================
typedef CUresult (*PFN_encodeTiled)(
    CUtensorMap*, CUtensorMapDataType, cuuint32_t, void*,
    const cuuint64_t*, const cuuint64_t*, const cuuint32_t*, const cuuint32_t*,
    CUtensorMapInterleave, CUtensorMapSwizzle, CUtensorMapL2promotion, CUtensorMapFloatOOBfill);

static void enc_map(PFN_encodeTiled fn, CUtensorMap* m, void* base,
                    uint64_t rows, uint64_t K, uint32_t boxRows)
{
    cuuint64_t dims[2]    = {K, rows};
    cuuint64_t strides[1] = {K * 2};
    cuuint32_t box[2]     = {64, boxRows};
    cuuint32_t es[2]      = {1, 1};
    fn(m, CU_TENSOR_MAP_DATA_TYPE_BFLOAT16, 2, base, dims, strides, box, es,
       CU_TENSOR_MAP_INTERLEAVE_NONE, CU_TENSOR_MAP_SWIZZLE_128B,
       CU_TENSOR_MAP_L2_PROMOTION_L2_128B, CU_TENSOR_MAP_FLOAT_OOB_FILL_NONE);
}

// ================= host launch =================
extern "C" void kernel_launch(void* const* d_in, const int* in_sizes, int n_in,
                              void* d_out, int out_size)
{
    const float* x      = (const float*)d_in[0];
    const float* ln1_g  = (const float*)d_in[1];
    const float* ln1_b  = (const float*)d_in[2];
    const float* ln2_g  = (const float*)d_in[3];
    const float* ln2_b  = (const float*)d_in[4];
    const float* wq     = (const float*)d_in[5];
    const float* wk     = (const float*)d_in[6];
    const float* wv     = (const float*)d_in[7];
    const float* proj_w = (const float*)d_in[8];
    const float* proj_b = (const float*)d_in[9];
    const float* fc1_w  = (const float*)d_in[10];
    const float* fc1_b  = (const float*)d_in[11];
    const float* fc2_w  = (const float*)d_in[12];
    const float* fc2_b  = (const float*)d_in[13];
    float* out = (float*)d_out;

    __nv_bfloat16 *h_hi,*h_lo,*o_hi,*o_lo,*h2_hi,*h2_lo,*act_hi,*act_lo;
    __nv_bfloat16 *qkvT_hi,*qkvT_lo,*pjT_hi,*pjT_lo,*f1T_hi,*f1T_lo,*f2T_hi,*f2T_lo;
    float *qkv,*x1,*attn;
    cudaGetSymbolAddress((void**)&h_hi,  g_h_hi);   cudaGetSymbolAddress((void**)&h_lo,  g_h_lo);
    cudaGetSymbolAddress((void**)&o_hi,  g_o_hi);   cudaGetSymbolAddress((void**)&o_lo,  g_o_lo);
    cudaGetSymbolAddress((void**)&h2_hi, g_h2_hi);  cudaGetSymbolAddress((void**)&h2_lo, g_h2_lo);
    cudaGetSymbolAddress((void**)&act_hi,g_act_hi); cudaGetSymbolAddress((void**)&act_lo,g_act_lo);
    cudaGetSymbolAddress((void**)&qkv, g_qkv);      cudaGetSymbolAddress((void**)&x1,  g_x1);
    cudaGetSymbolAddress((void**)&attn, g_attn);
    cudaGetSymbolAddress((void**)&qkvT_hi, g_qkvT_hi); cudaGetSymbolAddress((void**)&qkvT_lo, g_qkvT_lo);
    cudaGetSymbolAddress((void**)&pjT_hi,  g_pjT_hi);  cudaGetSymbolAddress((void**)&pjT_lo,  g_pjT_lo);
    cudaGetSymbolAddress((void**)&f1T_hi,  g_f1T_hi);  cudaGetSymbolAddress((void**)&f1T_lo,  g_f1T_lo);
    cudaGetSymbolAddress((void**)&f2T_hi,  g_f2T_hi);  cudaGetSymbolAddress((void**)&f2T_lo,  g_f2T_lo);

    // driver entry point for tensormap encoding (no -lcuda dependency)
    static PFN_encodeTiled enc_fn = nullptr;
    if (!enc_fn) {
        cudaDriverEntryPointQueryResult qr;
        void* fp = nullptr;
        cudaGetDriverEntryPoint("cuTensorMapEncodeTiled", &fp, cudaEnableDefault, &qr);
        enc_fn = (PFN_encodeTiled)fp;
    }

    // tensormaps (encoded host-side at capture time; passed by value)
    CUtensorMap mQKV_Ah, mQKV_Al, mQKV_Bh, mQKV_Bl;
    CUtensorMap mPJ_Ah,  mPJ_Al,  mPJ_Bh,  mPJ_Bl;
    CUtensorMap mF1_Ah,  mF1_Al,  mF1_Bh,  mF1_Bl;
    CUtensorMap mF2_Ah,  mF2_Al,  mF2_Bh,  mF2_Bl;
    enc_map(enc_fn, &mQKV_Ah, h_hi,   M_ROWS,     C_DIM,  128);
    enc_map(enc_fn, &mQKV_Al, h_lo,   M_ROWS,     C_DIM,  128);
    enc_map(enc_fn, &mQKV_Bh, qkvT_hi, QKV_STRIDE, C_DIM, 256);
    enc_map(enc_fn, &mQKV_Bl, qkvT_lo, QKV_STRIDE, C_DIM, 256);
    enc_map(enc_fn, &mPJ_Ah,  o_hi,   M_ROWS,     C_DIM,  128);
    enc_map(enc_fn, &mPJ_Al,  o_lo,   M_ROWS,     C_DIM,  128);
    enc_map(enc_fn, &mPJ_Bh,  pjT_hi, C_DIM,      C_DIM,  256);
    enc_map(enc_fn, &mPJ_Bl,  pjT_lo, C_DIM,      C_DIM,  256);
    enc_map(enc_fn, &mF1_Ah,  h2_hi,  M_ROWS,     C_DIM,  128);
    enc_map(enc_fn, &mF1_Al,  h2_lo,  M_ROWS,     C_DIM,  128);
    enc_map(enc_fn, &mF1_Bh,  f1T_hi, HF_DIM,     C_DIM,  256);
    enc_map(enc_fn, &mF1_Bl,  f1T_lo, HF_DIM,     C_DIM,  256);
    enc_map(enc_fn, &mF2_Ah,  act_hi, M_ROWS,     HF_DIM, 128);
    enc_map(enc_fn, &mF2_Al,  act_lo, M_ROWS,     HF_DIM, 128);
    enc_map(enc_fn, &mF2_Bh,  f2T_hi, C_DIM,      HF_DIM, 256);
    enc_map(enc_fn, &mF2_Bl,  f2T_lo, C_DIM,      HF_DIM, 256);

    cudaFuncSetAttribute(tgemm_kernel<0>, cudaFuncAttributeMaxDynamicSharedMemorySize, SMEM_BYTES_TOTAL);
    cudaFuncSetAttribute(tgemm_kernel<2>, cudaFuncAttributeMaxDynamicSharedMemorySize, SMEM_BYTES_TOTAL);
    cudaFuncSetAttribute(tgemm_kernel<3>, cudaFuncAttributeMaxDynamicSharedMemorySize, SMEM_BYTES_TOTAL);

    // weight prep (attention block first)
    trans_split_kernel<<<dim3(32,32),256>>>(wq,     qkvT_hi,               qkvT_lo,               1024, 1024);
    trans_split_kernel<<<dim3(32,32),256>>>(wk,     qkvT_hi + 1024 * 1024, qkvT_lo + 1024 * 1024, 1024, 1024);
    trans_split_kernel<<<dim3(32,32),256>>>(wv,     qkvT_hi + 2048 * 1024, qkvT_lo + 2048 * 1024, 1024, 1024);
    trans_split_kernel<<<dim3(32,32),256>>>(proj_w, pjT_hi,                pjT_lo,                1024, 1024);
    // LN1
    ln_split_kernel<<<M_ROWS, 256>>>(x, ln1_g, ln1_b, h_hi, h_lo);
    // fused QKV GEMM
    tgemm_kernel<0><<<dim3(QKV_STRIDE / BN, M_ROWS / BM), 256, SMEM_BYTES_TOTAL>>>(
        mQKV_Ah, mQKV_Al, mQKV_Bh, mQKV_Bl, nullptr, nullptr, qkv, nullptr, nullptr,
        M_ROWS, QKV_STRIDE, C_DIM);
    // attention
    scores_kernel<<<128, 256>>>(qkv, attn);
    av_kernel<<<dim3(128, 64), 256>>>(attn, qkv, o_hi, o_lo);
    // MLP weight prep
    trans_split_kernel<<<dim3(64,32),256>>>(fc1_w,  f1T_hi, f1T_lo, 1024, 2048);
    trans_split_kernel<<<dim3(32,64),256>>>(fc2_w,  f2T_hi, f2T_lo, 2048, 1024);
    // proj + bias + residual -> x1
    tgemm_kernel<2><<<dim3(C_DIM / BN, M_ROWS / BM), 256, SMEM_BYTES_TOTAL>>>(
        mPJ_Ah, mPJ_Al, mPJ_Bh, mPJ_Bl, proj_b, x, x1, nullptr, nullptr,
        M_ROWS, C_DIM, C_DIM);
    // LN2
    ln_split_kernel<<<M_ROWS, 256>>>(x1, ln2_g, ln2_b, h2_hi, h2_lo);
    // FC1 + bias + gelu
    tgemm_kernel<3><<<dim3(HF_DIM / BN, M_ROWS / BM), 256, SMEM_BYTES_TOTAL>>>(
        mF1_Ah, mF1_Al, mF1_Bh, mF1_Bl, fc1_b, nullptr, nullptr, act_hi, act_lo,
        M_ROWS, HF_DIM, C_DIM);
    // FC2 + bias + residual
    tgemm_kernel<2><<<dim3(C_DIM / BN, M_ROWS / BM), 256, SMEM_BYTES_TOTAL>>>(
        mF2_Ah, mF2_Al, mF2_Bh, mF2_Bl, fc2_b, x1, out, nullptr, nullptr,
        M_ROWS, C_DIM, HF_DIM);
}